// round 14
// baseline (speedup 1.0000x reference)
#include <cuda_runtime.h>
#include <math.h>

#define NN 12288
#define EE 393216
#define BB 16
#define CAP 96
#define INVN (1.0f/12288.0f)
#define PGRID 592            // 4 persistent blocks per SM x 148 SMs

// ---------------- device scratch ----------------
__device__ int2     g_cw[NN * CAP];                    // (col, ew bits) padded CSR
__device__ unsigned g_zb[2 * NN + 384 + BB * 64];      // degsum | cnt | stats(6x64) | embu
__device__ float    g_bufA[NN * 64];
__device__ float    g_bufB[NN * 64];
__device__ float    g_o1[BB * 512];
__device__ float    g_o2[BB * 256];

// ---------------- fused: edge weights + padded-CSR scatter  |  x@w1 ----------------
__global__ void __launch_bounds__(256) k_edgexw1(const float* __restrict__ ea,
                                                 const float* __restrict__ we,
                                                 const float* __restrict__ be,
                                                 const int* __restrict__ ei,
                                                 const float* __restrict__ x,
                                                 const float* __restrict__ w1,
                                                 float* __restrict__ degsum,
                                                 int* __restrict__ cnt) {
    if (blockIdx.x < EE / 256) {
        int e = blockIdx.x * 256 + threadIdx.x;
        float2 a = ((const float2*)ea)[e];
        float v = fmaf(a.x, __ldg(we), fmaf(a.y, __ldg(we + 1), __ldg(be)));
        float w = 1.0f / (1.0f + __expf(-v));
        int r = ei[e];
        int c = ei[EE + e];
        atomicAdd(&degsum[r], w);
        int p = atomicAdd(&cnt[r], 1);
        if (p < CAP) g_cw[r * CAP + p] = make_int2(c, __float_as_int(w));
    } else {
        __shared__ float Ws[15 * 32];
        int tid = threadIdx.x;
        for (int i = tid; i < 15 * 32; i += 256) Ws[i] = w1[i];
        __syncthreads();
        int node = (blockIdx.x - EE / 256) * 8 + (tid >> 5);
        int j = tid & 31;
        const float* xr = x + node * 15;
        float acc = 0.f;
#pragma unroll
        for (int k = 0; k < 15; k++) acc = fmaf(__ldg(xr + k), Ws[k * 32 + j], acc);
        g_bufA[node * 32 + j] = acc;
    }
}

// ---------------- spmm layer1 (F=32): persistent, premultiply, BN1 stats --------------
__global__ void __launch_bounds__(256) k_spmm1(const float* __restrict__ X,
                                               float* __restrict__ Y,
                                               const int* __restrict__ cnt,
                                               const float* __restrict__ degsum,
                                               float* __restrict__ stout) {
    __shared__ float s_sum[64], s_sq[64];
    int tid = threadIdx.x;
    if (tid < 64) { s_sum[tid] = 0.f; s_sq[tid] = 0.f; }
    __syncthreads();
    int lane = tid & 31;
    int q = lane & 7;
    int g = lane >> 3;
    const float4* X4 = (const float4*)X;

    for (int rb = blockIdx.x; rb < NN / 8; rb += PGRID) {
        int r = rb * 8 + (tid >> 5);

        auto proc = [&](int e, float4& a) {
            int2 cw = g_cw[e];
            float w = __int_as_float(cw.y) * rsqrtf(1.0f + degsum[cw.x]);
            if (q == 0) g_cw[e].y = __float_as_int(w);   // writeback premultiplied weight
            float4 xv = X4[cw.x * 8 + q];
            a.x = fmaf(w, xv.x, a.x);
            a.y = fmaf(w, xv.y, a.y);
            a.z = fmaf(w, xv.z, a.z);
            a.w = fmaf(w, xv.w, a.w);
        };

        int n = min(cnt[r], CAP);
        int base = r * CAP;
        float4 a0 = {0, 0, 0, 0}, a1 = a0, a2 = a0, a3 = a0;
        int k = g;
        for (; k + 12 < n; k += 16) {
            proc(base + k, a0);
            proc(base + k + 4, a1);
            proc(base + k + 8, a2);
            proc(base + k + 12, a3);
        }
        for (; k < n; k += 4) proc(base + k, a0);

        float4 acc;
        acc.x = (a0.x + a1.x) + (a2.x + a3.x);
        acc.y = (a0.y + a1.y) + (a2.y + a3.y);
        acc.z = (a0.z + a1.z) + (a2.z + a3.z);
        acc.w = (a0.w + a1.w) + (a2.w + a3.w);
#pragma unroll
        for (int off = 8; off < 32; off <<= 1) {
            acc.x += __shfl_xor_sync(0xffffffffu, acc.x, off);
            acc.y += __shfl_xor_sync(0xffffffffu, acc.y, off);
            acc.z += __shfl_xor_sync(0xffffffffu, acc.z, off);
            acc.w += __shfl_xor_sync(0xffffffffu, acc.w, off);
        }
        if (g == 0) {
            float dr = rsqrtf(1.0f + degsum[r]);
            float4 xr = X4[r * 8 + q];
            float4 v;
            v.x = dr * fmaf(dr, xr.x, acc.x);
            v.y = dr * fmaf(dr, xr.y, acc.y);
            v.z = dr * fmaf(dr, xr.z, acc.z);
            v.w = dr * fmaf(dr, xr.w, acc.w);
            ((float4*)Y)[r * 8 + q] = v;
            atomicAdd(&s_sum[4 * q + 0], v.x);
            atomicAdd(&s_sum[4 * q + 1], v.y);
            atomicAdd(&s_sum[4 * q + 2], v.z);
            atomicAdd(&s_sum[4 * q + 3], v.w);
            atomicAdd(&s_sq[4 * q + 0], v.x * v.x);
            atomicAdd(&s_sq[4 * q + 1], v.y * v.y);
            atomicAdd(&s_sq[4 * q + 2], v.z * v.z);
            atomicAdd(&s_sq[4 * q + 3], v.w * v.w);
        }
    }
    __syncthreads();
    if (tid < 32) {
        atomicAdd(&stout[tid], s_sum[tid]);
        atomicAdd(&stout[64 + tid], s_sq[tid]);
    }
}

// ---------------- layer2: persistent spmm(BN1+relu, F=32) + dense 32->64 + stats ------
__global__ void __launch_bounds__(256) k_sd32(const float* __restrict__ X,
                                              const float* __restrict__ W,
                                              float* __restrict__ Z,
                                              const int* __restrict__ cnt,
                                              const float* __restrict__ degsum,
                                              const float* __restrict__ bnst,
                                              const float* __restrict__ gamma,
                                              const float* __restrict__ beta,
                                              float* __restrict__ stout) {
    __shared__ float Ws[32 * 64];
    __shared__ float s_sum[64], s_sq[64];
    int tid = threadIdx.x;
    for (int i = tid; i < 32 * 64; i += 256) Ws[i] = W[i];
    if (tid < 64) { s_sum[tid] = 0.f; s_sq[tid] = 0.f; }
    __syncthreads();
    int lane = tid & 31;
    int q = lane & 7;
    int g = lane >> 3;

    float4 sc, sh;
    {
        float4 su = *(const float4*)(bnst + 4 * q);
        float4 sq = *(const float4*)(bnst + 64 + 4 * q);
        float4 ga = *(const float4*)(gamma + 4 * q);
        float4 bb = *(const float4*)(beta + 4 * q);
        float mx = su.x * INVN, my = su.y * INVN, mz = su.z * INVN, mw = su.w * INVN;
        sc.x = ga.x * rsqrtf(sq.x * INVN - mx * mx + 1e-5f);
        sc.y = ga.y * rsqrtf(sq.y * INVN - my * my + 1e-5f);
        sc.z = ga.z * rsqrtf(sq.z * INVN - mz * mz + 1e-5f);
        sc.w = ga.w * rsqrtf(sq.w * INVN - mw * mw + 1e-5f);
        sh.x = fmaf(-mx, sc.x, bb.x);
        sh.y = fmaf(-my, sc.y, bb.y);
        sh.z = fmaf(-mz, sc.z, bb.z);
        sh.w = fmaf(-mw, sc.w, bb.w);
    }

    const float4* X4 = (const float4*)X;
    for (int rb = blockIdx.x; rb < NN / 8; rb += PGRID) {
        int r = rb * 8 + (tid >> 5);

        auto proc = [&](int e, float4& a) {
            int2 cw = g_cw[e];
            float w = __int_as_float(cw.y);
            float4 xv = X4[cw.x * 8 + q];
            xv.x = fmaxf(0.f, fmaf(sc.x, xv.x, sh.x));
            xv.y = fmaxf(0.f, fmaf(sc.y, xv.y, sh.y));
            xv.z = fmaxf(0.f, fmaf(sc.z, xv.z, sh.z));
            xv.w = fmaxf(0.f, fmaf(sc.w, xv.w, sh.w));
            a.x = fmaf(w, xv.x, a.x);
            a.y = fmaf(w, xv.y, a.y);
            a.z = fmaf(w, xv.z, a.z);
            a.w = fmaf(w, xv.w, a.w);
        };

        int n = min(cnt[r], CAP);
        int base = r * CAP;
        float4 a0 = {0, 0, 0, 0}, a1 = a0, a2 = a0, a3 = a0;
        int k = g;
        for (; k + 12 < n; k += 16) {
            proc(base + k, a0);
            proc(base + k + 4, a1);
            proc(base + k + 8, a2);
            proc(base + k + 12, a3);
        }
        for (; k < n; k += 4) proc(base + k, a0);

        float4 acc;
        acc.x = (a0.x + a1.x) + (a2.x + a3.x);
        acc.y = (a0.y + a1.y) + (a2.y + a3.y);
        acc.z = (a0.z + a1.z) + (a2.z + a3.z);
        acc.w = (a0.w + a1.w) + (a2.w + a3.w);
#pragma unroll
        for (int off = 8; off < 32; off <<= 1) {
            acc.x += __shfl_xor_sync(0xffffffffu, acc.x, off);
            acc.y += __shfl_xor_sync(0xffffffffu, acc.y, off);
            acc.z += __shfl_xor_sync(0xffffffffu, acc.z, off);
            acc.w += __shfl_xor_sync(0xffffffffu, acc.w, off);
        }
        float dr = rsqrtf(1.0f + degsum[r]);
        float4 xr = X4[r * 8 + q];
        xr.x = fmaxf(0.f, fmaf(sc.x, xr.x, sh.x));
        xr.y = fmaxf(0.f, fmaf(sc.y, xr.y, sh.y));
        xr.z = fmaxf(0.f, fmaf(sc.z, xr.z, sh.z));
        xr.w = fmaxf(0.f, fmaf(sc.w, xr.w, sh.w));
        float4 vfin;
        vfin.x = dr * fmaf(dr, xr.x, acc.x);
        vfin.y = dr * fmaf(dr, xr.y, acc.y);
        vfin.z = dr * fmaf(dr, xr.z, acc.z);
        vfin.w = dr * fmaf(dr, xr.w, acc.w);

        float z0 = 0.f, z1 = 0.f;
#pragma unroll
        for (int k4 = 0; k4 < 8; k4++) {
            float4 vv;
            vv.x = __shfl_sync(0xffffffffu, vfin.x, k4);
            vv.y = __shfl_sync(0xffffffffu, vfin.y, k4);
            vv.z = __shfl_sync(0xffffffffu, vfin.z, k4);
            vv.w = __shfl_sync(0xffffffffu, vfin.w, k4);
            int kk = 4 * k4;
            z0 = fmaf(vv.x, Ws[(kk + 0) * 64 + lane], z0);
            z0 = fmaf(vv.y, Ws[(kk + 1) * 64 + lane], z0);
            z0 = fmaf(vv.z, Ws[(kk + 2) * 64 + lane], z0);
            z0 = fmaf(vv.w, Ws[(kk + 3) * 64 + lane], z0);
            z1 = fmaf(vv.x, Ws[(kk + 0) * 64 + lane + 32], z1);
            z1 = fmaf(vv.y, Ws[(kk + 1) * 64 + lane + 32], z1);
            z1 = fmaf(vv.z, Ws[(kk + 2) * 64 + lane + 32], z1);
            z1 = fmaf(vv.w, Ws[(kk + 3) * 64 + lane + 32], z1);
        }
        Z[r * 64 + lane] = z0;
        Z[r * 64 + lane + 32] = z1;
        atomicAdd(&s_sum[lane], z0);
        atomicAdd(&s_sq[lane], z0 * z0);
        atomicAdd(&s_sum[lane + 32], z1);
        atomicAdd(&s_sq[lane + 32], z1 * z1);
    }
    __syncthreads();
    if (tid < 64) {
        atomicAdd(&stout[tid], s_sum[tid]);
        atomicAdd(&stout[64 + tid], s_sq[tid]);
    }
}

// ---------------- layer3: persistent spmm(F=64, 8-way unroll) + dense 64->64 ----------
__global__ void __launch_bounds__(256) k_sd64(const float* __restrict__ X,
                                              const float* __restrict__ W,
                                              float* __restrict__ Z,
                                              const int* __restrict__ cnt,
                                              const float* __restrict__ degsum,
                                              const float* __restrict__ bnst,
                                              const float* __restrict__ gamma,
                                              const float* __restrict__ beta,
                                              float* __restrict__ stout) {
    __shared__ float Ws[64 * 64];
    __shared__ float s_sum[64], s_sq[64];
    int tid = threadIdx.x;
    for (int i = tid; i < 64 * 64; i += 256) Ws[i] = W[i];
    if (tid < 64) { s_sum[tid] = 0.f; s_sq[tid] = 0.f; }
    __syncthreads();
    int lane = tid & 31;
    int q = lane & 15;              // float4 slot over 64 features
    int g = lane >> 4;              // edge group 0..1

    float4 sc, sh;
    {
        float4 su = *(const float4*)(bnst + 4 * q);
        float4 sq = *(const float4*)(bnst + 64 + 4 * q);
        float4 ga = *(const float4*)(gamma + 4 * q);
        float4 bb = *(const float4*)(beta + 4 * q);
        float mx = su.x * INVN, my = su.y * INVN, mz = su.z * INVN, mw = su.w * INVN;
        sc.x = ga.x * rsqrtf(sq.x * INVN - mx * mx + 1e-5f);
        sc.y = ga.y * rsqrtf(sq.y * INVN - my * my + 1e-5f);
        sc.z = ga.z * rsqrtf(sq.z * INVN - mz * mz + 1e-5f);
        sc.w = ga.w * rsqrtf(sq.w * INVN - mw * mw + 1e-5f);
        sh.x = fmaf(-mx, sc.x, bb.x);
        sh.y = fmaf(-my, sc.y, bb.y);
        sh.z = fmaf(-mz, sc.z, bb.z);
        sh.w = fmaf(-mw, sc.w, bb.w);
    }

    const float4* X4 = (const float4*)X;
    for (int rb = blockIdx.x; rb < NN / 8; rb += PGRID) {
        int r = rb * 8 + (tid >> 5);

        auto proc = [&](int e, float4& a) {
            int2 cw = g_cw[e];
            float w = __int_as_float(cw.y);
            float4 xv = X4[cw.x * 16 + q];
            xv.x = fmaxf(0.f, fmaf(sc.x, xv.x, sh.x));
            xv.y = fmaxf(0.f, fmaf(sc.y, xv.y, sh.y));
            xv.z = fmaxf(0.f, fmaf(sc.z, xv.z, sh.z));
            xv.w = fmaxf(0.f, fmaf(sc.w, xv.w, sh.w));
            a.x = fmaf(w, xv.x, a.x);
            a.y = fmaf(w, xv.y, a.y);
            a.z = fmaf(w, xv.z, a.z);
            a.w = fmaf(w, xv.w, a.w);
        };

        int n = min(cnt[r], CAP);
        int base = r * CAP;
        float4 a0 = {0, 0, 0, 0}, a1 = a0, a2 = a0, a3 = a0;
        float4 a4 = a0, a5 = a0, a6 = a0, a7 = a0;
        int k = g;
        for (; k + 14 < n; k += 16) {       // 8 chains x G=2 stride = 16 chains/row
            proc(base + k, a0);
            proc(base + k + 2, a1);
            proc(base + k + 4, a2);
            proc(base + k + 6, a3);
            proc(base + k + 8, a4);
            proc(base + k + 10, a5);
            proc(base + k + 12, a6);
            proc(base + k + 14, a7);
        }
        for (; k < n; k += 2) proc(base + k, a0);

        float4 acc;
        acc.x = ((a0.x + a1.x) + (a2.x + a3.x)) + ((a4.x + a5.x) + (a6.x + a7.x));
        acc.y = ((a0.y + a1.y) + (a2.y + a3.y)) + ((a4.y + a5.y) + (a6.y + a7.y));
        acc.z = ((a0.z + a1.z) + (a2.z + a3.z)) + ((a4.z + a5.z) + (a6.z + a7.z));
        acc.w = ((a0.w + a1.w) + (a2.w + a3.w)) + ((a4.w + a5.w) + (a6.w + a7.w));
        acc.x += __shfl_xor_sync(0xffffffffu, acc.x, 16);
        acc.y += __shfl_xor_sync(0xffffffffu, acc.y, 16);
        acc.z += __shfl_xor_sync(0xffffffffu, acc.z, 16);
        acc.w += __shfl_xor_sync(0xffffffffu, acc.w, 16);

        float dr = rsqrtf(1.0f + degsum[r]);
        float4 xr = X4[r * 16 + q];
        xr.x = fmaxf(0.f, fmaf(sc.x, xr.x, sh.x));
        xr.y = fmaxf(0.f, fmaf(sc.y, xr.y, sh.y));
        xr.z = fmaxf(0.f, fmaf(sc.z, xr.z, sh.z));
        xr.w = fmaxf(0.f, fmaf(sc.w, xr.w, sh.w));
        float4 vfin;
        vfin.x = dr * fmaf(dr, xr.x, acc.x);
        vfin.y = dr * fmaf(dr, xr.y, acc.y);
        vfin.z = dr * fmaf(dr, xr.z, acc.z);
        vfin.w = dr * fmaf(dr, xr.w, acc.w);

        // dense 64->64: lanes q and q+16 hold identical vfin; broadcast from lanes 0..15
        float z0 = 0.f, z1 = 0.f;
#pragma unroll
        for (int k4 = 0; k4 < 16; k4++) {
            float4 vv;
            vv.x = __shfl_sync(0xffffffffu, vfin.x, k4);
            vv.y = __shfl_sync(0xffffffffu, vfin.y, k4);
            vv.z = __shfl_sync(0xffffffffu, vfin.z, k4);
            vv.w = __shfl_sync(0xffffffffu, vfin.w, k4);
            int kk = 4 * k4;
            z0 = fmaf(vv.x, Ws[(kk + 0) * 64 + lane], z0);
            z0 = fmaf(vv.y, Ws[(kk + 1) * 64 + lane], z0);
            z0 = fmaf(vv.z, Ws[(kk + 2) * 64 + lane], z0);
            z0 = fmaf(vv.w, Ws[(kk + 3) * 64 + lane], z0);
            z1 = fmaf(vv.x, Ws[(kk + 0) * 64 + lane + 32], z1);
            z1 = fmaf(vv.y, Ws[(kk + 1) * 64 + lane + 32], z1);
            z1 = fmaf(vv.z, Ws[(kk + 2) * 64 + lane + 32], z1);
            z1 = fmaf(vv.w, Ws[(kk + 3) * 64 + lane + 32], z1);
        }
        Z[r * 64 + lane] = z0;
        Z[r * 64 + lane + 32] = z1;
        atomicAdd(&s_sum[lane], z0);
        atomicAdd(&s_sq[lane], z0 * z0);
        atomicAdd(&s_sum[lane + 32], z1);
        atomicAdd(&s_sq[lane + 32], z1 * z1);
    }
    __syncthreads();
    if (tid < 64) {
        atomicAdd(&stout[tid], s_sum[tid]);
        atomicAdd(&stout[64 + tid], s_sq[tid]);
    }
}

// ---------------- BN3 + ReLU + two-stage per-graph max pool ----------------
__global__ void __launch_bounds__(256) k_pool(const float* __restrict__ Z,
                                              const int* __restrict__ batch,
                                              const float* __restrict__ bnst,
                                              const float* __restrict__ gamma,
                                              const float* __restrict__ beta,
                                              unsigned* __restrict__ embu) {
    int tid = threadIdx.x;
    int f = tid & 63;
    int sub = tid >> 6;
    int node0 = blockIdx.x * 32;
    float su = bnst[f], sq = bnst[64 + f];
    float mu = su * INVN;
    float scv = gamma[f] * rsqrtf(sq * INVN - mu * mu + 1e-5f);
    float shv = fmaf(-mu, scv, beta[f]);
    int curb = batch[node0 + sub];
    float m = 0.f;
#pragma unroll
    for (int i = 0; i < 8; i++) {
        int node = node0 + sub + 4 * i;
        int b = batch[node];
        float v = fmaxf(0.f, fmaf(scv, Z[node * 64 + f], shv));
        if (b != curb) {
            atomicMax(&embu[curb * 64 + f], __float_as_uint(m));
            m = 0.f;
            curb = b;
        }
        m = fmaxf(m, v);
    }
    atomicMax(&embu[curb * 64 + f], __float_as_uint(m));
}

// ---------------- MLP layer: (r,j)-parallel, shuffle BN over 16 rows ----------------
template <int FI, int FO, bool CVT>
__global__ void __launch_bounds__(256) k_mlp(const void* __restrict__ Xin,
                                             const float* __restrict__ W,
                                             const float* __restrict__ gamma,
                                             const float* __restrict__ beta,
                                             float* __restrict__ Y,
                                             float* __restrict__ out, int out_size) {
    __shared__ float Xs[BB * FI];
    int tid = threadIdx.x;
    for (int i = tid; i < BB * FI; i += 256) {
        float v = CVT ? __uint_as_float(((const unsigned*)Xin)[i]) : ((const float*)Xin)[i];
        Xs[i] = v;
        if (CVT && blockIdx.x == 0) {
            int o = BB * 11 + i;
            if (o < out_size) out[o] = v;
        }
    }
    __syncthreads();
    int r = tid & 15;
    int jl = tid >> 4;
    int j = blockIdx.x * 16 + jl;
    float acc = 0.f;
    for (int k = 0; k < FI; k++) acc = fmaf(Xs[r * FI + k], __ldg(W + k * FO + j), acc);
    float s = acc, s2 = acc * acc;
#pragma unroll
    for (int off = 1; off < 16; off <<= 1) {
        s  += __shfl_xor_sync(0xffffffffu, s, off);
        s2 += __shfl_xor_sync(0xffffffffu, s2, off);
    }
    float mu = s * (1.0f / BB);
    float var = s2 * (1.0f / BB) - mu * mu;
    float scv = gamma[j] * rsqrtf(var + 1e-5f);
    float shv = fmaf(-mu, scv, beta[j]);
    Y[r * FO + j] = fmaxf(0.f, fmaf(scv, acc, shv));
}

// ---------------- final linear + log_softmax ----------------
__global__ void k_head(const float* __restrict__ X, const float* __restrict__ W,
                       const float* __restrict__ bias, float* __restrict__ out, int out_size) {
    __shared__ float L[BB * 11];
    __shared__ float mrow[BB], lrow[BB];
    int tid = threadIdx.x;
    if (tid < BB * 11) {
        int r = tid / 11, c = tid % 11;
        float acc = bias[c];
        for (int k = 0; k < 256; k++) acc = fmaf(X[r * 256 + k], __ldg(W + k * 11 + c), acc);
        L[tid] = acc;
    }
    __syncthreads();
    if (tid < BB) {
        float m = -1e30f;
        for (int c = 0; c < 11; c++) m = fmaxf(m, L[tid * 11 + c]);
        float s = 0.f;
        for (int c = 0; c < 11; c++) s += expf(L[tid * 11 + c] - m);
        mrow[tid] = m;
        lrow[tid] = logf(s);
    }
    __syncthreads();
    if (tid < BB * 11 && tid < out_size) {
        int r = tid / 11;
        out[tid] = L[tid] - mrow[r] - lrow[r];
    }
}

// ---------------- launch ----------------
extern "C" void kernel_launch(void* const* d_in, const int* in_sizes, int n_in,
                              void* d_out, int out_size) {
    const float* x    = (const float*)d_in[0];
    const float* ea   = (const float*)d_in[1];
    const float* we   = (const float*)d_in[2];
    const float* be   = (const float*)d_in[3];
    const float* w1   = (const float*)d_in[4];
    const float* g1   = (const float*)d_in[6];
    const float* be1  = (const float*)d_in[7];
    const float* w2   = (const float*)d_in[8];
    const float* g2   = (const float*)d_in[10];
    const float* be2  = (const float*)d_in[11];
    const float* w3   = (const float*)d_in[12];
    const float* g3   = (const float*)d_in[14];
    const float* be3  = (const float*)d_in[15];
    const float* wf1  = (const float*)d_in[16];
    const float* gf1  = (const float*)d_in[18];
    const float* bef1 = (const float*)d_in[19];
    const float* wf2  = (const float*)d_in[20];
    const float* gf2  = (const float*)d_in[22];
    const float* bef2 = (const float*)d_in[23];
    const float* wf3  = (const float*)d_in[24];
    const float* bf3  = (const float*)d_in[25];
    const int*   ei   = (const int*)d_in[26];
    const int*   batch= (const int*)d_in[27];
    float* out = (float*)d_out;

    void *pz, *pa, *pb, *po1, *po2;
    cudaGetSymbolAddress(&pz, g_zb);
    cudaGetSymbolAddress(&pa, g_bufA);
    cudaGetSymbolAddress(&pb, g_bufB);
    cudaGetSymbolAddress(&po1, g_o1);
    cudaGetSymbolAddress(&po2, g_o2);
    unsigned* zb = (unsigned*)pz;
    float* degsum = (float*)zb;
    int* cnt = (int*)(zb + NN);
    float* stats = (float*)(zb + 2 * NN);          // S1@0, S2@128, S3@256 (sum@+0, sq@+64)
    unsigned* embu = zb + 2 * NN + 384;
    float* bufA = (float*)pa;
    float* bufB = (float*)pb;
    float* o1 = (float*)po1;
    float* o2 = (float*)po2;

    cudaMemsetAsync(pz, 0, sizeof(unsigned) * (2 * NN + 384 + BB * 64));
    k_edgexw1<<<EE / 256 + NN / 8, 256>>>(ea, we, be, ei, x, w1, degsum, cnt);
    // layer 1: persistent spmm over x@w1 (premultiplies weights), BN1 stats
    k_spmm1<<<PGRID, 256>>>(bufA, bufB, cnt, degsum, stats);
    // layer 2: persistent spmm(BN1+relu) fused with dense 32->64, BN2 stats
    k_sd32<<<PGRID, 256>>>(bufB, w2, bufA, cnt, degsum, stats, g1, be1, stats + 128);
    // layer 3: persistent spmm(BN2+relu) fused with dense 64->64, BN3 stats
    k_sd64<<<PGRID, 256>>>(bufA, w3, bufB, cnt, degsum, stats + 128, g2, be2, stats + 256);
    // BN3 + relu + two-stage global max pool
    k_pool<<<NN / 32, 256>>>(bufB, batch, stats + 256, g3, be3, embu);
    // MLP head (emb conversion + emb output fused into mlp1)
    k_mlp<64, 512, true><<<32, 256>>>(embu, wf1, gf1, bef1, o1, out, out_size);
    k_mlp<512, 256, false><<<16, 256>>>(o1, wf2, gf2, bef2, o2, out, out_size);
    k_head<<<1, 192>>>(o2, wf3, bf3, out, out_size);
}

// round 15
// speedup vs baseline: 1.3914x; 1.3914x over previous
#include <cuda_runtime.h>
#include <math.h>

#define NN 12288
#define EE 393216
#define BB 16
#define CAP 96
#define INVN (1.0f/12288.0f)

// ---------------- device scratch ----------------
__device__ int2     g_cw[NN * CAP];                    // (col, ew bits) padded CSR
__device__ unsigned g_zb[2 * NN + 384 + BB * 64];      // degsum | cnt | stats(6x64) | embu
__device__ float    g_bufA[NN * 64];
__device__ float    g_bufB[NN * 64];
__device__ float    g_o1[BB * 512];
__device__ float    g_o2[BB * 256];

// ---------------- fused: edge weights + padded-CSR scatter  |  x@w1 ----------------
__global__ void __launch_bounds__(256) k_edgexw1(const float* __restrict__ ea,
                                                 const float* __restrict__ we,
                                                 const float* __restrict__ be,
                                                 const int* __restrict__ ei,
                                                 const float* __restrict__ x,
                                                 const float* __restrict__ w1,
                                                 float* __restrict__ degsum,
                                                 int* __restrict__ cnt) {
    if (blockIdx.x < EE / 256) {
        int e = blockIdx.x * 256 + threadIdx.x;
        float2 a = ((const float2*)ea)[e];
        float v = fmaf(a.x, __ldg(we), fmaf(a.y, __ldg(we + 1), __ldg(be)));
        float w = 1.0f / (1.0f + __expf(-v));
        int r = ei[e];
        int c = ei[EE + e];
        atomicAdd(&degsum[r], w);
        int p = atomicAdd(&cnt[r], 1);
        if (p < CAP) g_cw[r * CAP + p] = make_int2(c, __float_as_int(w));
    } else {
        __shared__ float Ws[15 * 32];
        int tid = threadIdx.x;
        for (int i = tid; i < 15 * 32; i += 256) Ws[i] = w1[i];
        __syncthreads();
        int node = (blockIdx.x - EE / 256) * 8 + (tid >> 5);
        int j = tid & 31;
        const float* xr = x + node * 15;
        float acc = 0.f;
#pragma unroll
        for (int k = 0; k < 15; k++) acc = fmaf(__ldg(xr + k), Ws[k * 32 + j], acc);
        g_bufA[node * 32 + j] = acc;
    }
}

// ---------------- spmm layer1 (F=32): 32 chains, premultiply, BN1 stats ---------------
__global__ void __launch_bounds__(256) k_spmm1(const float* __restrict__ X,
                                               float* __restrict__ Y,
                                               const int* __restrict__ cnt,
                                               const float* __restrict__ degsum,
                                               float* __restrict__ stout) {
    __shared__ float s_sum[64], s_sq[64];
    int tid = threadIdx.x;
    if (tid < 64) { s_sum[tid] = 0.f; s_sq[tid] = 0.f; }
    __syncthreads();
    int lane = tid & 31;
    int q = lane & 7;
    int g = lane >> 3;
    int r = blockIdx.x * 8 + (tid >> 5);

    const float4* X4 = (const float4*)X;
    auto proc = [&](int e, float4& a) {
        int2 cw = g_cw[e];
        float w = __int_as_float(cw.y) * rsqrtf(1.0f + degsum[cw.x]);
        if (q == 0) g_cw[e].y = __float_as_int(w);   // writeback premultiplied weight
        float4 xv = X4[cw.x * 8 + q];
        a.x = fmaf(w, xv.x, a.x);
        a.y = fmaf(w, xv.y, a.y);
        a.z = fmaf(w, xv.z, a.z);
        a.w = fmaf(w, xv.w, a.w);
    };

    int n = min(cnt[r], CAP);
    int base = r * CAP;
    float4 a0 = {0, 0, 0, 0}, a1 = a0, a2 = a0, a3 = a0;
    float4 a4 = a0, a5 = a0, a6 = a0, a7 = a0;
    int k = g;
    for (; k + 28 < n; k += 32) {       // 8 chains x G=4 stride = 32 chains/row
        proc(base + k, a0);
        proc(base + k + 4, a1);
        proc(base + k + 8, a2);
        proc(base + k + 12, a3);
        proc(base + k + 16, a4);
        proc(base + k + 20, a5);
        proc(base + k + 24, a6);
        proc(base + k + 28, a7);
    }
    for (; k < n; k += 4) proc(base + k, a0);

    float4 acc;
    acc.x = ((a0.x + a1.x) + (a2.x + a3.x)) + ((a4.x + a5.x) + (a6.x + a7.x));
    acc.y = ((a0.y + a1.y) + (a2.y + a3.y)) + ((a4.y + a5.y) + (a6.y + a7.y));
    acc.z = ((a0.z + a1.z) + (a2.z + a3.z)) + ((a4.z + a5.z) + (a6.z + a7.z));
    acc.w = ((a0.w + a1.w) + (a2.w + a3.w)) + ((a4.w + a5.w) + (a6.w + a7.w));
#pragma unroll
    for (int off = 8; off < 32; off <<= 1) {
        acc.x += __shfl_xor_sync(0xffffffffu, acc.x, off);
        acc.y += __shfl_xor_sync(0xffffffffu, acc.y, off);
        acc.z += __shfl_xor_sync(0xffffffffu, acc.z, off);
        acc.w += __shfl_xor_sync(0xffffffffu, acc.w, off);
    }
    if (g == 0) {
        float dr = rsqrtf(1.0f + degsum[r]);
        float4 xr = X4[r * 8 + q];
        float4 v;
        v.x = dr * fmaf(dr, xr.x, acc.x);
        v.y = dr * fmaf(dr, xr.y, acc.y);
        v.z = dr * fmaf(dr, xr.z, acc.z);
        v.w = dr * fmaf(dr, xr.w, acc.w);
        ((float4*)Y)[r * 8 + q] = v;
        atomicAdd(&s_sum[4 * q + 0], v.x);
        atomicAdd(&s_sum[4 * q + 1], v.y);
        atomicAdd(&s_sum[4 * q + 2], v.z);
        atomicAdd(&s_sum[4 * q + 3], v.w);
        atomicAdd(&s_sq[4 * q + 0], v.x * v.x);
        atomicAdd(&s_sq[4 * q + 1], v.y * v.y);
        atomicAdd(&s_sq[4 * q + 2], v.z * v.z);
        atomicAdd(&s_sq[4 * q + 3], v.w * v.w);
    }
    __syncthreads();
    if (tid < 32) {
        atomicAdd(&stout[tid], s_sum[tid]);
        atomicAdd(&stout[64 + tid], s_sq[tid]);
    }
}

// ---------------- layer2: spmm(BN1+relu, F=32, 32 chains) + dense 32->64 + stats ------
__global__ void __launch_bounds__(256) k_sd32(const float* __restrict__ X,
                                              const float* __restrict__ W,
                                              float* __restrict__ Z,
                                              const int* __restrict__ cnt,
                                              const float* __restrict__ degsum,
                                              const float* __restrict__ bnst,
                                              const float* __restrict__ gamma,
                                              const float* __restrict__ beta,
                                              float* __restrict__ stout) {
    __shared__ float Ws[32 * 64];
    __shared__ float s_sum[64], s_sq[64];
    int tid = threadIdx.x;
    for (int i = tid; i < 32 * 64; i += 256) Ws[i] = W[i];
    if (tid < 64) { s_sum[tid] = 0.f; s_sq[tid] = 0.f; }
    __syncthreads();
    int lane = tid & 31;
    int q = lane & 7;
    int g = lane >> 3;
    int r = blockIdx.x * 8 + (tid >> 5);

    float4 sc, sh;
    {
        float4 su = *(const float4*)(bnst + 4 * q);
        float4 sq = *(const float4*)(bnst + 64 + 4 * q);
        float4 ga = *(const float4*)(gamma + 4 * q);
        float4 bb = *(const float4*)(beta + 4 * q);
        float mx = su.x * INVN, my = su.y * INVN, mz = su.z * INVN, mw = su.w * INVN;
        sc.x = ga.x * rsqrtf(sq.x * INVN - mx * mx + 1e-5f);
        sc.y = ga.y * rsqrtf(sq.y * INVN - my * my + 1e-5f);
        sc.z = ga.z * rsqrtf(sq.z * INVN - mz * mz + 1e-5f);
        sc.w = ga.w * rsqrtf(sq.w * INVN - mw * mw + 1e-5f);
        sh.x = fmaf(-mx, sc.x, bb.x);
        sh.y = fmaf(-my, sc.y, bb.y);
        sh.z = fmaf(-mz, sc.z, bb.z);
        sh.w = fmaf(-mw, sc.w, bb.w);
    }

    const float4* X4 = (const float4*)X;
    auto proc = [&](int e, float4& a) {
        int2 cw = g_cw[e];
        float w = __int_as_float(cw.y);
        float4 xv = X4[cw.x * 8 + q];
        xv.x = fmaxf(0.f, fmaf(sc.x, xv.x, sh.x));
        xv.y = fmaxf(0.f, fmaf(sc.y, xv.y, sh.y));
        xv.z = fmaxf(0.f, fmaf(sc.z, xv.z, sh.z));
        xv.w = fmaxf(0.f, fmaf(sc.w, xv.w, sh.w));
        a.x = fmaf(w, xv.x, a.x);
        a.y = fmaf(w, xv.y, a.y);
        a.z = fmaf(w, xv.z, a.z);
        a.w = fmaf(w, xv.w, a.w);
    };

    int n = min(cnt[r], CAP);
    int base = r * CAP;
    float4 a0 = {0, 0, 0, 0}, a1 = a0, a2 = a0, a3 = a0;
    float4 a4 = a0, a5 = a0, a6 = a0, a7 = a0;
    int k = g;
    for (; k + 28 < n; k += 32) {       // 8 chains x G=4 stride = 32 chains/row
        proc(base + k, a0);
        proc(base + k + 4, a1);
        proc(base + k + 8, a2);
        proc(base + k + 12, a3);
        proc(base + k + 16, a4);
        proc(base + k + 20, a5);
        proc(base + k + 24, a6);
        proc(base + k + 28, a7);
    }
    for (; k < n; k += 4) proc(base + k, a0);

    float4 acc;
    acc.x = ((a0.x + a1.x) + (a2.x + a3.x)) + ((a4.x + a5.x) + (a6.x + a7.x));
    acc.y = ((a0.y + a1.y) + (a2.y + a3.y)) + ((a4.y + a5.y) + (a6.y + a7.y));
    acc.z = ((a0.z + a1.z) + (a2.z + a3.z)) + ((a4.z + a5.z) + (a6.z + a7.z));
    acc.w = ((a0.w + a1.w) + (a2.w + a3.w)) + ((a4.w + a5.w) + (a6.w + a7.w));
#pragma unroll
    for (int off = 8; off < 32; off <<= 1) {
        acc.x += __shfl_xor_sync(0xffffffffu, acc.x, off);
        acc.y += __shfl_xor_sync(0xffffffffu, acc.y, off);
        acc.z += __shfl_xor_sync(0xffffffffu, acc.z, off);
        acc.w += __shfl_xor_sync(0xffffffffu, acc.w, off);
    }
    float dr = rsqrtf(1.0f + degsum[r]);
    float4 xr = X4[r * 8 + q];
    xr.x = fmaxf(0.f, fmaf(sc.x, xr.x, sh.x));
    xr.y = fmaxf(0.f, fmaf(sc.y, xr.y, sh.y));
    xr.z = fmaxf(0.f, fmaf(sc.z, xr.z, sh.z));
    xr.w = fmaxf(0.f, fmaf(sc.w, xr.w, sh.w));
    float4 vfin;
    vfin.x = dr * fmaf(dr, xr.x, acc.x);
    vfin.y = dr * fmaf(dr, xr.y, acc.y);
    vfin.z = dr * fmaf(dr, xr.z, acc.z);
    vfin.w = dr * fmaf(dr, xr.w, acc.w);

    float z0 = 0.f, z1 = 0.f;
#pragma unroll
    for (int k4 = 0; k4 < 8; k4++) {
        float4 vv;
        vv.x = __shfl_sync(0xffffffffu, vfin.x, k4);
        vv.y = __shfl_sync(0xffffffffu, vfin.y, k4);
        vv.z = __shfl_sync(0xffffffffu, vfin.z, k4);
        vv.w = __shfl_sync(0xffffffffu, vfin.w, k4);
        int kk = 4 * k4;
        z0 = fmaf(vv.x, Ws[(kk + 0) * 64 + lane], z0);
        z0 = fmaf(vv.y, Ws[(kk + 1) * 64 + lane], z0);
        z0 = fmaf(vv.z, Ws[(kk + 2) * 64 + lane], z0);
        z0 = fmaf(vv.w, Ws[(kk + 3) * 64 + lane], z0);
        z1 = fmaf(vv.x, Ws[(kk + 0) * 64 + lane + 32], z1);
        z1 = fmaf(vv.y, Ws[(kk + 1) * 64 + lane + 32], z1);
        z1 = fmaf(vv.z, Ws[(kk + 2) * 64 + lane + 32], z1);
        z1 = fmaf(vv.w, Ws[(kk + 3) * 64 + lane + 32], z1);
    }
    Z[r * 64 + lane] = z0;
    Z[r * 64 + lane + 32] = z1;
    atomicAdd(&s_sum[lane], z0);
    atomicAdd(&s_sq[lane], z0 * z0);
    atomicAdd(&s_sum[lane + 32], z1);
    atomicAdd(&s_sq[lane + 32], z1 * z1);
    __syncthreads();
    if (tid < 64) {
        atomicAdd(&stout[tid], s_sum[tid]);
        atomicAdd(&stout[64 + tid], s_sq[tid]);
    }
}

// ---------------- layer3: spmm(F=64, 1 warp/row, 8-way unroll) + dense 64->64 ---------
__global__ void __launch_bounds__(256) k_sd64(const float* __restrict__ X,
                                              const float* __restrict__ W,
                                              float* __restrict__ Z,
                                              const int* __restrict__ cnt,
                                              const float* __restrict__ degsum,
                                              const float* __restrict__ bnst,
                                              const float* __restrict__ gamma,
                                              const float* __restrict__ beta,
                                              float* __restrict__ stout) {
    __shared__ float Ws[64 * 64];
    __shared__ float s_sum[64], s_sq[64];
    int tid = threadIdx.x;
    for (int i = tid; i < 64 * 64; i += 256) Ws[i] = W[i];
    if (tid < 64) { s_sum[tid] = 0.f; s_sq[tid] = 0.f; }
    __syncthreads();
    int lane = tid & 31;
    int q = lane & 15;              // float4 slot over 64 features
    int g = lane >> 4;              // edge group 0..1
    int r = blockIdx.x * 8 + (tid >> 5);

    float4 sc, sh;
    {
        float4 su = *(const float4*)(bnst + 4 * q);
        float4 sq = *(const float4*)(bnst + 64 + 4 * q);
        float4 ga = *(const float4*)(gamma + 4 * q);
        float4 bb = *(const float4*)(beta + 4 * q);
        float mx = su.x * INVN, my = su.y * INVN, mz = su.z * INVN, mw = su.w * INVN;
        sc.x = ga.x * rsqrtf(sq.x * INVN - mx * mx + 1e-5f);
        sc.y = ga.y * rsqrtf(sq.y * INVN - my * my + 1e-5f);
        sc.z = ga.z * rsqrtf(sq.z * INVN - mz * mz + 1e-5f);
        sc.w = ga.w * rsqrtf(sq.w * INVN - mw * mw + 1e-5f);
        sh.x = fmaf(-mx, sc.x, bb.x);
        sh.y = fmaf(-my, sc.y, bb.y);
        sh.z = fmaf(-mz, sc.z, bb.z);
        sh.w = fmaf(-mw, sc.w, bb.w);
    }

    const float4* X4 = (const float4*)X;
    auto proc = [&](int e, float4& a) {
        int2 cw = g_cw[e];
        float w = __int_as_float(cw.y);
        float4 xv = X4[cw.x * 16 + q];
        xv.x = fmaxf(0.f, fmaf(sc.x, xv.x, sh.x));
        xv.y = fmaxf(0.f, fmaf(sc.y, xv.y, sh.y));
        xv.z = fmaxf(0.f, fmaf(sc.z, xv.z, sh.z));
        xv.w = fmaxf(0.f, fmaf(sc.w, xv.w, sh.w));
        a.x = fmaf(w, xv.x, a.x);
        a.y = fmaf(w, xv.y, a.y);
        a.z = fmaf(w, xv.z, a.z);
        a.w = fmaf(w, xv.w, a.w);
    };

    int n = min(cnt[r], CAP);
    int base = r * CAP;
    float4 a0 = {0, 0, 0, 0}, a1 = a0, a2 = a0, a3 = a0;
    float4 a4 = a0, a5 = a0, a6 = a0, a7 = a0;
    int k = g;
    for (; k + 14 < n; k += 16) {       // 8 chains x G=2 stride = 16 chains/row
        proc(base + k, a0);
        proc(base + k + 2, a1);
        proc(base + k + 4, a2);
        proc(base + k + 6, a3);
        proc(base + k + 8, a4);
        proc(base + k + 10, a5);
        proc(base + k + 12, a6);
        proc(base + k + 14, a7);
    }
    for (; k < n; k += 2) proc(base + k, a0);

    float4 acc;
    acc.x = ((a0.x + a1.x) + (a2.x + a3.x)) + ((a4.x + a5.x) + (a6.x + a7.x));
    acc.y = ((a0.y + a1.y) + (a2.y + a3.y)) + ((a4.y + a5.y) + (a6.y + a7.y));
    acc.z = ((a0.z + a1.z) + (a2.z + a3.z)) + ((a4.z + a5.z) + (a6.z + a7.z));
    acc.w = ((a0.w + a1.w) + (a2.w + a3.w)) + ((a4.w + a5.w) + (a6.w + a7.w));
    acc.x += __shfl_xor_sync(0xffffffffu, acc.x, 16);
    acc.y += __shfl_xor_sync(0xffffffffu, acc.y, 16);
    acc.z += __shfl_xor_sync(0xffffffffu, acc.z, 16);
    acc.w += __shfl_xor_sync(0xffffffffu, acc.w, 16);

    float dr = rsqrtf(1.0f + degsum[r]);
    float4 xr = X4[r * 16 + q];
    xr.x = fmaxf(0.f, fmaf(sc.x, xr.x, sh.x));
    xr.y = fmaxf(0.f, fmaf(sc.y, xr.y, sh.y));
    xr.z = fmaxf(0.f, fmaf(sc.z, xr.z, sh.z));
    xr.w = fmaxf(0.f, fmaf(sc.w, xr.w, sh.w));
    float4 vfin;
    vfin.x = dr * fmaf(dr, xr.x, acc.x);
    vfin.y = dr * fmaf(dr, xr.y, acc.y);
    vfin.z = dr * fmaf(dr, xr.z, acc.z);
    vfin.w = dr * fmaf(dr, xr.w, acc.w);

    // dense 64->64: lanes q and q+16 hold identical vfin; broadcast from lanes 0..15
    float z0 = 0.f, z1 = 0.f;
#pragma unroll
    for (int k4 = 0; k4 < 16; k4++) {
        float4 vv;
        vv.x = __shfl_sync(0xffffffffu, vfin.x, k4);
        vv.y = __shfl_sync(0xffffffffu, vfin.y, k4);
        vv.z = __shfl_sync(0xffffffffu, vfin.z, k4);
        vv.w = __shfl_sync(0xffffffffu, vfin.w, k4);
        int kk = 4 * k4;
        z0 = fmaf(vv.x, Ws[(kk + 0) * 64 + lane], z0);
        z0 = fmaf(vv.y, Ws[(kk + 1) * 64 + lane], z0);
        z0 = fmaf(vv.z, Ws[(kk + 2) * 64 + lane], z0);
        z0 = fmaf(vv.w, Ws[(kk + 3) * 64 + lane], z0);
        z1 = fmaf(vv.x, Ws[(kk + 0) * 64 + lane + 32], z1);
        z1 = fmaf(vv.y, Ws[(kk + 1) * 64 + lane + 32], z1);
        z1 = fmaf(vv.z, Ws[(kk + 2) * 64 + lane + 32], z1);
        z1 = fmaf(vv.w, Ws[(kk + 3) * 64 + lane + 32], z1);
    }
    Z[r * 64 + lane] = z0;
    Z[r * 64 + lane + 32] = z1;
    atomicAdd(&s_sum[lane], z0);
    atomicAdd(&s_sq[lane], z0 * z0);
    atomicAdd(&s_sum[lane + 32], z1);
    atomicAdd(&s_sq[lane + 32], z1 * z1);
    __syncthreads();
    if (tid < 64) {
        atomicAdd(&stout[tid], s_sum[tid]);
        atomicAdd(&stout[64 + tid], s_sq[tid]);
    }
}

// ---------------- BN3 + ReLU + two-stage per-graph max pool ----------------
__global__ void __launch_bounds__(256) k_pool(const float* __restrict__ Z,
                                              const int* __restrict__ batch,
                                              const float* __restrict__ bnst,
                                              const float* __restrict__ gamma,
                                              const float* __restrict__ beta,
                                              unsigned* __restrict__ embu) {
    int tid = threadIdx.x;
    int f = tid & 63;
    int sub = tid >> 6;
    int node0 = blockIdx.x * 32;
    float su = bnst[f], sq = bnst[64 + f];
    float mu = su * INVN;
    float scv = gamma[f] * rsqrtf(sq * INVN - mu * mu + 1e-5f);
    float shv = fmaf(-mu, scv, beta[f]);
    int curb = batch[node0 + sub];
    float m = 0.f;
#pragma unroll
    for (int i = 0; i < 8; i++) {
        int node = node0 + sub + 4 * i;
        int b = batch[node];
        float v = fmaxf(0.f, fmaf(scv, Z[node * 64 + f], shv));
        if (b != curb) {
            atomicMax(&embu[curb * 64 + f], __float_as_uint(m));
            m = 0.f;
            curb = b;
        }
        m = fmaxf(m, v);
    }
    atomicMax(&embu[curb * 64 + f], __float_as_uint(m));
}

// ---------------- MLP layer: (r,j)-parallel, shuffle BN over 16 rows ----------------
template <int FI, int FO, bool CVT>
__global__ void __launch_bounds__(256) k_mlp(const void* __restrict__ Xin,
                                             const float* __restrict__ W,
                                             const float* __restrict__ gamma,
                                             const float* __restrict__ beta,
                                             float* __restrict__ Y,
                                             float* __restrict__ out, int out_size) {
    __shared__ float Xs[BB * FI];
    int tid = threadIdx.x;
    for (int i = tid; i < BB * FI; i += 256) {
        float v = CVT ? __uint_as_float(((const unsigned*)Xin)[i]) : ((const float*)Xin)[i];
        Xs[i] = v;
        if (CVT && blockIdx.x == 0) {
            int o = BB * 11 + i;
            if (o < out_size) out[o] = v;
        }
    }
    __syncthreads();
    int r = tid & 15;
    int jl = tid >> 4;
    int j = blockIdx.x * 16 + jl;
    float acc = 0.f;
    for (int k = 0; k < FI; k++) acc = fmaf(Xs[r * FI + k], __ldg(W + k * FO + j), acc);
    float s = acc, s2 = acc * acc;
#pragma unroll
    for (int off = 1; off < 16; off <<= 1) {
        s  += __shfl_xor_sync(0xffffffffu, s, off);
        s2 += __shfl_xor_sync(0xffffffffu, s2, off);
    }
    float mu = s * (1.0f / BB);
    float var = s2 * (1.0f / BB) - mu * mu;
    float scv = gamma[j] * rsqrtf(var + 1e-5f);
    float shv = fmaf(-mu, scv, beta[j]);
    Y[r * FO + j] = fmaxf(0.f, fmaf(scv, acc, shv));
}

// ---------------- final linear + log_softmax ----------------
__global__ void k_head(const float* __restrict__ X, const float* __restrict__ W,
                       const float* __restrict__ bias, float* __restrict__ out, int out_size) {
    __shared__ float L[BB * 11];
    __shared__ float mrow[BB], lrow[BB];
    int tid = threadIdx.x;
    if (tid < BB * 11) {
        int r = tid / 11, c = tid % 11;
        float acc = bias[c];
        for (int k = 0; k < 256; k++) acc = fmaf(X[r * 256 + k], __ldg(W + k * 11 + c), acc);
        L[tid] = acc;
    }
    __syncthreads();
    if (tid < BB) {
        float m = -1e30f;
        for (int c = 0; c < 11; c++) m = fmaxf(m, L[tid * 11 + c]);
        float s = 0.f;
        for (int c = 0; c < 11; c++) s += expf(L[tid * 11 + c] - m);
        mrow[tid] = m;
        lrow[tid] = logf(s);
    }
    __syncthreads();
    if (tid < BB * 11 && tid < out_size) {
        int r = tid / 11;
        out[tid] = L[tid] - mrow[r] - lrow[r];
    }
}

// ---------------- launch ----------------
extern "C" void kernel_launch(void* const* d_in, const int* in_sizes, int n_in,
                              void* d_out, int out_size) {
    const float* x    = (const float*)d_in[0];
    const float* ea   = (const float*)d_in[1];
    const float* we   = (const float*)d_in[2];
    const float* be   = (const float*)d_in[3];
    const float* w1   = (const float*)d_in[4];
    const float* g1   = (const float*)d_in[6];
    const float* be1  = (const float*)d_in[7];
    const float* w2   = (const float*)d_in[8];
    const float* g2   = (const float*)d_in[10];
    const float* be2  = (const float*)d_in[11];
    const float* w3   = (const float*)d_in[12];
    const float* g3   = (const float*)d_in[14];
    const float* be3  = (const float*)d_in[15];
    const float* wf1  = (const float*)d_in[16];
    const float* gf1  = (const float*)d_in[18];
    const float* bef1 = (const float*)d_in[19];
    const float* wf2  = (const float*)d_in[20];
    const float* gf2  = (const float*)d_in[22];
    const float* bef2 = (const float*)d_in[23];
    const float* wf3  = (const float*)d_in[24];
    const float* bf3  = (const float*)d_in[25];
    const int*   ei   = (const int*)d_in[26];
    const int*   batch= (const int*)d_in[27];
    float* out = (float*)d_out;

    void *pz, *pa, *pb, *po1, *po2;
    cudaGetSymbolAddress(&pz, g_zb);
    cudaGetSymbolAddress(&pa, g_bufA);
    cudaGetSymbolAddress(&pb, g_bufB);
    cudaGetSymbolAddress(&po1, g_o1);
    cudaGetSymbolAddress(&po2, g_o2);
    unsigned* zb = (unsigned*)pz;
    float* degsum = (float*)zb;
    int* cnt = (int*)(zb + NN);
    float* stats = (float*)(zb + 2 * NN);          // S1@0, S2@128, S3@256 (sum@+0, sq@+64)
    unsigned* embu = zb + 2 * NN + 384;
    float* bufA = (float*)pa;
    float* bufB = (float*)pb;
    float* o1 = (float*)po1;
    float* o2 = (float*)po2;

    cudaMemsetAsync(pz, 0, sizeof(unsigned) * (2 * NN + 384 + BB * 64));
    k_edgexw1<<<EE / 256 + NN / 8, 256>>>(ea, we, be, ei, x, w1, degsum, cnt);
    // layer 1: spmm over x@w1 (32 chains, premultiplies weights), BN1 stats
    k_spmm1<<<NN / 8, 256>>>(bufA, bufB, cnt, degsum, stats);
    // layer 2: spmm(BN1+relu, 32 chains) fused with dense 32->64, BN2 stats
    k_sd32<<<NN / 8, 256>>>(bufB, w2, bufA, cnt, degsum, stats, g1, be1, stats + 128);
    // layer 3: spmm(BN2+relu, 16 chains) fused with dense 64->64, BN3 stats
    k_sd64<<<NN / 8, 256>>>(bufA, w3, bufB, cnt, degsum, stats + 128, g2, be2, stats + 256);
    // BN3 + relu + two-stage global max pool
    k_pool<<<NN / 32, 256>>>(bufB, batch, stats + 256, g3, be3, embu);
    // MLP head (emb conversion + emb output fused into mlp1)
    k_mlp<64, 512, true><<<32, 256>>>(embu, wf1, gf1, bef1, o1, out, out_size);
    k_mlp<512, 256, false><<<16, 256>>>(o1, wf2, gf2, bef2, o2, out, out_size);
    k_head<<<1, 192>>>(o2, wf3, bf3, out, out_size);
}

// round 16
// speedup vs baseline: 1.4203x; 1.0208x over previous
#include <cuda_runtime.h>
#include <cuda_fp16.h>
#include <math.h>

#define NN 12288
#define EE 393216
#define BB 16
#define CAP 96
#define INVN (1.0f/12288.0f)

// ---------------- device scratch ----------------
__device__ int2     g_cw[NN * CAP];                    // (col, ew bits) padded CSR
__device__ unsigned g_zb[2 * NN + 384 + BB * 64];      // degsum | cnt | stats(6x64) | embu
__device__ float    g_bufA[NN * 64];                   // also reused as half[NN*64] for layer2 out
__device__ float    g_bufB[NN * 64];
__device__ float    g_o1[BB * 512];
__device__ float    g_o2[BB * 256];

// ---------------- fused: edge weights + padded-CSR scatter  |  x@w1 ----------------
__global__ void __launch_bounds__(256) k_edgexw1(const float* __restrict__ ea,
                                                 const float* __restrict__ we,
                                                 const float* __restrict__ be,
                                                 const int* __restrict__ ei,
                                                 const float* __restrict__ x,
                                                 const float* __restrict__ w1,
                                                 float* __restrict__ degsum,
                                                 int* __restrict__ cnt) {
    if (blockIdx.x < EE / 256) {
        int e = blockIdx.x * 256 + threadIdx.x;
        float2 a = ((const float2*)ea)[e];
        float v = fmaf(a.x, __ldg(we), fmaf(a.y, __ldg(we + 1), __ldg(be)));
        float w = 1.0f / (1.0f + __expf(-v));
        int r = ei[e];
        int c = ei[EE + e];
        atomicAdd(&degsum[r], w);
        int p = atomicAdd(&cnt[r], 1);
        if (p < CAP) g_cw[r * CAP + p] = make_int2(c, __float_as_int(w));
    } else {
        __shared__ float Ws[15 * 32];
        int tid = threadIdx.x;
        for (int i = tid; i < 15 * 32; i += 256) Ws[i] = w1[i];
        __syncthreads();
        int node = (blockIdx.x - EE / 256) * 8 + (tid >> 5);
        int j = tid & 31;
        const float* xr = x + node * 15;
        float acc = 0.f;
#pragma unroll
        for (int k = 0; k < 15; k++) acc = fmaf(__ldg(xr + k), Ws[k * 32 + j], acc);
        g_bufA[node * 32 + j] = acc;
    }
}

// ---------------- spmm layer1 (F=32): 32 chains, premultiply, BN1 stats ---------------
__global__ void __launch_bounds__(256) k_spmm1(const float* __restrict__ X,
                                               float* __restrict__ Y,
                                               const int* __restrict__ cnt,
                                               const float* __restrict__ degsum,
                                               float* __restrict__ stout) {
    __shared__ float s_sum[64], s_sq[64];
    int tid = threadIdx.x;
    if (tid < 64) { s_sum[tid] = 0.f; s_sq[tid] = 0.f; }
    __syncthreads();
    int lane = tid & 31;
    int q = lane & 7;
    int g = lane >> 3;
    int r = blockIdx.x * 8 + (tid >> 5);

    const float4* X4 = (const float4*)X;
    auto proc = [&](int e, float4& a) {
        int2 cw = g_cw[e];
        float w = __int_as_float(cw.y) * rsqrtf(1.0f + degsum[cw.x]);
        if (q == 0) g_cw[e].y = __float_as_int(w);   // writeback premultiplied weight
        float4 xv = X4[cw.x * 8 + q];
        a.x = fmaf(w, xv.x, a.x);
        a.y = fmaf(w, xv.y, a.y);
        a.z = fmaf(w, xv.z, a.z);
        a.w = fmaf(w, xv.w, a.w);
    };

    int n = min(cnt[r], CAP);
    int base = r * CAP;
    float4 a0 = {0, 0, 0, 0}, a1 = a0, a2 = a0, a3 = a0;
    float4 a4 = a0, a5 = a0, a6 = a0, a7 = a0;
    int k = g;
    for (; k + 28 < n; k += 32) {
        proc(base + k, a0);
        proc(base + k + 4, a1);
        proc(base + k + 8, a2);
        proc(base + k + 12, a3);
        proc(base + k + 16, a4);
        proc(base + k + 20, a5);
        proc(base + k + 24, a6);
        proc(base + k + 28, a7);
    }
    for (; k < n; k += 4) proc(base + k, a0);

    float4 acc;
    acc.x = ((a0.x + a1.x) + (a2.x + a3.x)) + ((a4.x + a5.x) + (a6.x + a7.x));
    acc.y = ((a0.y + a1.y) + (a2.y + a3.y)) + ((a4.y + a5.y) + (a6.y + a7.y));
    acc.z = ((a0.z + a1.z) + (a2.z + a3.z)) + ((a4.z + a5.z) + (a6.z + a7.z));
    acc.w = ((a0.w + a1.w) + (a2.w + a3.w)) + ((a4.w + a5.w) + (a6.w + a7.w));
#pragma unroll
    for (int off = 8; off < 32; off <<= 1) {
        acc.x += __shfl_xor_sync(0xffffffffu, acc.x, off);
        acc.y += __shfl_xor_sync(0xffffffffu, acc.y, off);
        acc.z += __shfl_xor_sync(0xffffffffu, acc.z, off);
        acc.w += __shfl_xor_sync(0xffffffffu, acc.w, off);
    }
    if (g == 0) {
        float dr = rsqrtf(1.0f + degsum[r]);
        float4 xr = X4[r * 8 + q];
        float4 v;
        v.x = dr * fmaf(dr, xr.x, acc.x);
        v.y = dr * fmaf(dr, xr.y, acc.y);
        v.z = dr * fmaf(dr, xr.z, acc.z);
        v.w = dr * fmaf(dr, xr.w, acc.w);
        ((float4*)Y)[r * 8 + q] = v;
        atomicAdd(&s_sum[4 * q + 0], v.x);
        atomicAdd(&s_sum[4 * q + 1], v.y);
        atomicAdd(&s_sum[4 * q + 2], v.z);
        atomicAdd(&s_sum[4 * q + 3], v.w);
        atomicAdd(&s_sq[4 * q + 0], v.x * v.x);
        atomicAdd(&s_sq[4 * q + 1], v.y * v.y);
        atomicAdd(&s_sq[4 * q + 2], v.z * v.z);
        atomicAdd(&s_sq[4 * q + 3], v.w * v.w);
    }
    __syncthreads();
    if (tid < 32) {
        atomicAdd(&stout[tid], s_sum[tid]);
        atomicAdd(&stout[64 + tid], s_sq[tid]);
    }
}

// ---------------- layer2: spmm(BN1+relu, F=32) + dense 32->64 -> HALF out + stats -----
__global__ void __launch_bounds__(256) k_sd32(const float* __restrict__ X,
                                              const float* __restrict__ W,
                                              __half* __restrict__ Zh,
                                              const int* __restrict__ cnt,
                                              const float* __restrict__ degsum,
                                              const float* __restrict__ bnst,
                                              const float* __restrict__ gamma,
                                              const float* __restrict__ beta,
                                              float* __restrict__ stout) {
    __shared__ float Ws[32 * 64];
    __shared__ float s_sum[64], s_sq[64];
    int tid = threadIdx.x;
    for (int i = tid; i < 32 * 64; i += 256) Ws[i] = W[i];
    if (tid < 64) { s_sum[tid] = 0.f; s_sq[tid] = 0.f; }
    __syncthreads();
    int lane = tid & 31;
    int q = lane & 7;
    int g = lane >> 3;
    int r = blockIdx.x * 8 + (tid >> 5);

    float4 sc, sh;
    {
        float4 su = *(const float4*)(bnst + 4 * q);
        float4 sq = *(const float4*)(bnst + 64 + 4 * q);
        float4 ga = *(const float4*)(gamma + 4 * q);
        float4 bb = *(const float4*)(beta + 4 * q);
        float mx = su.x * INVN, my = su.y * INVN, mz = su.z * INVN, mw = su.w * INVN;
        sc.x = ga.x * rsqrtf(sq.x * INVN - mx * mx + 1e-5f);
        sc.y = ga.y * rsqrtf(sq.y * INVN - my * my + 1e-5f);
        sc.z = ga.z * rsqrtf(sq.z * INVN - mz * mz + 1e-5f);
        sc.w = ga.w * rsqrtf(sq.w * INVN - mw * mw + 1e-5f);
        sh.x = fmaf(-mx, sc.x, bb.x);
        sh.y = fmaf(-my, sc.y, bb.y);
        sh.z = fmaf(-mz, sc.z, bb.z);
        sh.w = fmaf(-mw, sc.w, bb.w);
    }

    const float4* X4 = (const float4*)X;
    auto proc = [&](int e, float4& a) {
        int2 cw = g_cw[e];
        float w = __int_as_float(cw.y);
        float4 xv = X4[cw.x * 8 + q];
        xv.x = fmaxf(0.f, fmaf(sc.x, xv.x, sh.x));
        xv.y = fmaxf(0.f, fmaf(sc.y, xv.y, sh.y));
        xv.z = fmaxf(0.f, fmaf(sc.z, xv.z, sh.z));
        xv.w = fmaxf(0.f, fmaf(sc.w, xv.w, sh.w));
        a.x = fmaf(w, xv.x, a.x);
        a.y = fmaf(w, xv.y, a.y);
        a.z = fmaf(w, xv.z, a.z);
        a.w = fmaf(w, xv.w, a.w);
    };

    int n = min(cnt[r], CAP);
    int base = r * CAP;
    float4 a0 = {0, 0, 0, 0}, a1 = a0, a2 = a0, a3 = a0;
    float4 a4 = a0, a5 = a0, a6 = a0, a7 = a0;
    int k = g;
    for (; k + 28 < n; k += 32) {
        proc(base + k, a0);
        proc(base + k + 4, a1);
        proc(base + k + 8, a2);
        proc(base + k + 12, a3);
        proc(base + k + 16, a4);
        proc(base + k + 20, a5);
        proc(base + k + 24, a6);
        proc(base + k + 28, a7);
    }
    for (; k < n; k += 4) proc(base + k, a0);

    float4 acc;
    acc.x = ((a0.x + a1.x) + (a2.x + a3.x)) + ((a4.x + a5.x) + (a6.x + a7.x));
    acc.y = ((a0.y + a1.y) + (a2.y + a3.y)) + ((a4.y + a5.y) + (a6.y + a7.y));
    acc.z = ((a0.z + a1.z) + (a2.z + a3.z)) + ((a4.z + a5.z) + (a6.z + a7.z));
    acc.w = ((a0.w + a1.w) + (a2.w + a3.w)) + ((a4.w + a5.w) + (a6.w + a7.w));
#pragma unroll
    for (int off = 8; off < 32; off <<= 1) {
        acc.x += __shfl_xor_sync(0xffffffffu, acc.x, off);
        acc.y += __shfl_xor_sync(0xffffffffu, acc.y, off);
        acc.z += __shfl_xor_sync(0xffffffffu, acc.z, off);
        acc.w += __shfl_xor_sync(0xffffffffu, acc.w, off);
    }
    float dr = rsqrtf(1.0f + degsum[r]);
    float4 xr = X4[r * 8 + q];
    xr.x = fmaxf(0.f, fmaf(sc.x, xr.x, sh.x));
    xr.y = fmaxf(0.f, fmaf(sc.y, xr.y, sh.y));
    xr.z = fmaxf(0.f, fmaf(sc.z, xr.z, sh.z));
    xr.w = fmaxf(0.f, fmaf(sc.w, xr.w, sh.w));
    float4 vfin;
    vfin.x = dr * fmaf(dr, xr.x, acc.x);
    vfin.y = dr * fmaf(dr, xr.y, acc.y);
    vfin.z = dr * fmaf(dr, xr.z, acc.z);
    vfin.w = dr * fmaf(dr, xr.w, acc.w);

    float z0 = 0.f, z1 = 0.f;
#pragma unroll
    for (int k4 = 0; k4 < 8; k4++) {
        float4 vv;
        vv.x = __shfl_sync(0xffffffffu, vfin.x, k4);
        vv.y = __shfl_sync(0xffffffffu, vfin.y, k4);
        vv.z = __shfl_sync(0xffffffffu, vfin.z, k4);
        vv.w = __shfl_sync(0xffffffffu, vfin.w, k4);
        int kk = 4 * k4;
        z0 = fmaf(vv.x, Ws[(kk + 0) * 64 + lane], z0);
        z0 = fmaf(vv.y, Ws[(kk + 1) * 64 + lane], z0);
        z0 = fmaf(vv.z, Ws[(kk + 2) * 64 + lane], z0);
        z0 = fmaf(vv.w, Ws[(kk + 3) * 64 + lane], z0);
        z1 = fmaf(vv.x, Ws[(kk + 0) * 64 + lane + 32], z1);
        z1 = fmaf(vv.y, Ws[(kk + 1) * 64 + lane + 32], z1);
        z1 = fmaf(vv.z, Ws[(kk + 2) * 64 + lane + 32], z1);
        z1 = fmaf(vv.w, Ws[(kk + 3) * 64 + lane + 32], z1);
    }
    Zh[r * 64 + lane] = __float2half(z0);
    Zh[r * 64 + lane + 32] = __float2half(z1);
    atomicAdd(&s_sum[lane], z0);
    atomicAdd(&s_sq[lane], z0 * z0);
    atomicAdd(&s_sum[lane + 32], z1);
    atomicAdd(&s_sq[lane + 32], z1 * z1);
    __syncthreads();
    if (tid < 64) {
        atomicAdd(&stout[tid], s_sum[tid]);
        atomicAdd(&stout[64 + tid], s_sq[tid]);
    }
}

// ---------------- layer3: spmm(F=64 HALF input, 16 chains) + dense 64->64 -------------
__global__ void __launch_bounds__(256) k_sd64(const __half* __restrict__ Xh,
                                              const float* __restrict__ W,
                                              float* __restrict__ Z,
                                              const int* __restrict__ cnt,
                                              const float* __restrict__ degsum,
                                              const float* __restrict__ bnst,
                                              const float* __restrict__ gamma,
                                              const float* __restrict__ beta,
                                              float* __restrict__ stout) {
    __shared__ float Ws[64 * 64];
    __shared__ float s_sum[64], s_sq[64];
    int tid = threadIdx.x;
    for (int i = tid; i < 64 * 64; i += 256) Ws[i] = W[i];
    if (tid < 64) { s_sum[tid] = 0.f; s_sq[tid] = 0.f; }
    __syncthreads();
    int lane = tid & 31;
    int q = lane & 15;              // 8-byte slot over 64 half features
    int g = lane >> 4;              // edge group 0..1
    int r = blockIdx.x * 8 + (tid >> 5);

    float4 sc, sh;
    {
        float4 su = *(const float4*)(bnst + 4 * q);
        float4 sq = *(const float4*)(bnst + 64 + 4 * q);
        float4 ga = *(const float4*)(gamma + 4 * q);
        float4 bb = *(const float4*)(beta + 4 * q);
        float mx = su.x * INVN, my = su.y * INVN, mz = su.z * INVN, mw = su.w * INVN;
        sc.x = ga.x * rsqrtf(sq.x * INVN - mx * mx + 1e-5f);
        sc.y = ga.y * rsqrtf(sq.y * INVN - my * my + 1e-5f);
        sc.z = ga.z * rsqrtf(sq.z * INVN - mz * mz + 1e-5f);
        sc.w = ga.w * rsqrtf(sq.w * INVN - mw * mw + 1e-5f);
        sh.x = fmaf(-mx, sc.x, bb.x);
        sh.y = fmaf(-my, sc.y, bb.y);
        sh.z = fmaf(-mz, sc.z, bb.z);
        sh.w = fmaf(-mw, sc.w, bb.w);
    }

    const uint2* X2 = (const uint2*)Xh;    // one uint2 = 4 halves = features 4q..4q+3
    auto proc = [&](int e, float4& a) {
        int2 cw = g_cw[e];
        float w = __int_as_float(cw.y);
        uint2 hv = X2[cw.x * 16 + q];
        float2 f0 = __half22float2(*(const __half2*)&hv.x);
        float2 f1 = __half22float2(*(const __half2*)&hv.y);
        float vx = fmaxf(0.f, fmaf(sc.x, f0.x, sh.x));
        float vy = fmaxf(0.f, fmaf(sc.y, f0.y, sh.y));
        float vz = fmaxf(0.f, fmaf(sc.z, f1.x, sh.z));
        float vw = fmaxf(0.f, fmaf(sc.w, f1.y, sh.w));
        a.x = fmaf(w, vx, a.x);
        a.y = fmaf(w, vy, a.y);
        a.z = fmaf(w, vz, a.z);
        a.w = fmaf(w, vw, a.w);
    };

    int n = min(cnt[r], CAP);
    int base = r * CAP;
    float4 a0 = {0, 0, 0, 0}, a1 = a0, a2 = a0, a3 = a0;
    float4 a4 = a0, a5 = a0, a6 = a0, a7 = a0;
    int k = g;
    for (; k + 14 < n; k += 16) {       // 8 chains x G=2 stride = 16 chains/row
        proc(base + k, a0);
        proc(base + k + 2, a1);
        proc(base + k + 4, a2);
        proc(base + k + 6, a3);
        proc(base + k + 8, a4);
        proc(base + k + 10, a5);
        proc(base + k + 12, a6);
        proc(base + k + 14, a7);
    }
    for (; k < n; k += 2) proc(base + k, a0);

    float4 acc;
    acc.x = ((a0.x + a1.x) + (a2.x + a3.x)) + ((a4.x + a5.x) + (a6.x + a7.x));
    acc.y = ((a0.y + a1.y) + (a2.y + a3.y)) + ((a4.y + a5.y) + (a6.y + a7.y));
    acc.z = ((a0.z + a1.z) + (a2.z + a3.z)) + ((a4.z + a5.z) + (a6.z + a7.z));
    acc.w = ((a0.w + a1.w) + (a2.w + a3.w)) + ((a4.w + a5.w) + (a6.w + a7.w));
    acc.x += __shfl_xor_sync(0xffffffffu, acc.x, 16);
    acc.y += __shfl_xor_sync(0xffffffffu, acc.y, 16);
    acc.z += __shfl_xor_sync(0xffffffffu, acc.z, 16);
    acc.w += __shfl_xor_sync(0xffffffffu, acc.w, 16);

    float dr = rsqrtf(1.0f + degsum[r]);
    uint2 hr = X2[r * 16 + q];
    float2 r0 = __half22float2(*(const __half2*)&hr.x);
    float2 r1 = __half22float2(*(const __half2*)&hr.y);
    float rx = fmaxf(0.f, fmaf(sc.x, r0.x, sh.x));
    float ry = fmaxf(0.f, fmaf(sc.y, r0.y, sh.y));
    float rz = fmaxf(0.f, fmaf(sc.z, r1.x, sh.z));
    float rw = fmaxf(0.f, fmaf(sc.w, r1.y, sh.w));
    float4 vfin;
    vfin.x = dr * fmaf(dr, rx, acc.x);
    vfin.y = dr * fmaf(dr, ry, acc.y);
    vfin.z = dr * fmaf(dr, rz, acc.z);
    vfin.w = dr * fmaf(dr, rw, acc.w);

    // dense 64->64: lanes q and q+16 hold identical vfin; broadcast from lanes 0..15
    float z0 = 0.f, z1 = 0.f;
#pragma unroll
    for (int k4 = 0; k4 < 16; k4++) {
        float4 vv;
        vv.x = __shfl_sync(0xffffffffu, vfin.x, k4);
        vv.y = __shfl_sync(0xffffffffu, vfin.y, k4);
        vv.z = __shfl_sync(0xffffffffu, vfin.z, k4);
        vv.w = __shfl_sync(0xffffffffu, vfin.w, k4);
        int kk = 4 * k4;
        z0 = fmaf(vv.x, Ws[(kk + 0) * 64 + lane], z0);
        z0 = fmaf(vv.y, Ws[(kk + 1) * 64 + lane], z0);
        z0 = fmaf(vv.z, Ws[(kk + 2) * 64 + lane], z0);
        z0 = fmaf(vv.w, Ws[(kk + 3) * 64 + lane], z0);
        z1 = fmaf(vv.x, Ws[(kk + 0) * 64 + lane + 32], z1);
        z1 = fmaf(vv.y, Ws[(kk + 1) * 64 + lane + 32], z1);
        z1 = fmaf(vv.z, Ws[(kk + 2) * 64 + lane + 32], z1);
        z1 = fmaf(vv.w, Ws[(kk + 3) * 64 + lane + 32], z1);
    }
    Z[r * 64 + lane] = z0;
    Z[r * 64 + lane + 32] = z1;
    atomicAdd(&s_sum[lane], z0);
    atomicAdd(&s_sq[lane], z0 * z0);
    atomicAdd(&s_sum[lane + 32], z1);
    atomicAdd(&s_sq[lane + 32], z1 * z1);
    __syncthreads();
    if (tid < 64) {
        atomicAdd(&stout[tid], s_sum[tid]);
        atomicAdd(&stout[64 + tid], s_sq[tid]);
    }
}

// ---------------- BN3 + ReLU + two-stage per-graph max pool ----------------
__global__ void __launch_bounds__(256) k_pool(const float* __restrict__ Z,
                                              const int* __restrict__ batch,
                                              const float* __restrict__ bnst,
                                              const float* __restrict__ gamma,
                                              const float* __restrict__ beta,
                                              unsigned* __restrict__ embu) {
    int tid = threadIdx.x;
    int f = tid & 63;
    int sub = tid >> 6;
    int node0 = blockIdx.x * 32;
    float su = bnst[f], sq = bnst[64 + f];
    float mu = su * INVN;
    float scv = gamma[f] * rsqrtf(sq * INVN - mu * mu + 1e-5f);
    float shv = fmaf(-mu, scv, beta[f]);
    int curb = batch[node0 + sub];
    float m = 0.f;
#pragma unroll
    for (int i = 0; i < 8; i++) {
        int node = node0 + sub + 4 * i;
        int b = batch[node];
        float v = fmaxf(0.f, fmaf(scv, Z[node * 64 + f], shv));
        if (b != curb) {
            atomicMax(&embu[curb * 64 + f], __float_as_uint(m));
            m = 0.f;
            curb = b;
        }
        m = fmaxf(m, v);
    }
    atomicMax(&embu[curb * 64 + f], __float_as_uint(m));
}

// ---------------- MLP layer: (r,j)-parallel, shuffle BN over 16 rows ----------------
template <int FI, int FO, bool CVT>
__global__ void __launch_bounds__(256) k_mlp(const void* __restrict__ Xin,
                                             const float* __restrict__ W,
                                             const float* __restrict__ gamma,
                                             const float* __restrict__ beta,
                                             float* __restrict__ Y,
                                             float* __restrict__ out, int out_size) {
    __shared__ float Xs[BB * FI];
    int tid = threadIdx.x;
    for (int i = tid; i < BB * FI; i += 256) {
        float v = CVT ? __uint_as_float(((const unsigned*)Xin)[i]) : ((const float*)Xin)[i];
        Xs[i] = v;
        if (CVT && blockIdx.x == 0) {
            int o = BB * 11 + i;
            if (o < out_size) out[o] = v;
        }
    }
    __syncthreads();
    int r = tid & 15;
    int jl = tid >> 4;
    int j = blockIdx.x * 16 + jl;
    float acc = 0.f;
    for (int k = 0; k < FI; k++) acc = fmaf(Xs[r * FI + k], __ldg(W + k * FO + j), acc);
    float s = acc, s2 = acc * acc;
#pragma unroll
    for (int off = 1; off < 16; off <<= 1) {
        s  += __shfl_xor_sync(0xffffffffu, s, off);
        s2 += __shfl_xor_sync(0xffffffffu, s2, off);
    }
    float mu = s * (1.0f / BB);
    float var = s2 * (1.0f / BB) - mu * mu;
    float scv = gamma[j] * rsqrtf(var + 1e-5f);
    float shv = fmaf(-mu, scv, beta[j]);
    Y[r * FO + j] = fmaxf(0.f, fmaf(scv, acc, shv));
}

// ---------------- final linear + log_softmax ----------------
__global__ void k_head(const float* __restrict__ X, const float* __restrict__ W,
                       const float* __restrict__ bias, float* __restrict__ out, int out_size) {
    __shared__ float L[BB * 11];
    __shared__ float mrow[BB], lrow[BB];
    int tid = threadIdx.x;
    if (tid < BB * 11) {
        int r = tid / 11, c = tid % 11;
        float acc = bias[c];
        for (int k = 0; k < 256; k++) acc = fmaf(X[r * 256 + k], __ldg(W + k * 11 + c), acc);
        L[tid] = acc;
    }
    __syncthreads();
    if (tid < BB) {
        float m = -1e30f;
        for (int c = 0; c < 11; c++) m = fmaxf(m, L[tid * 11 + c]);
        float s = 0.f;
        for (int c = 0; c < 11; c++) s += expf(L[tid * 11 + c] - m);
        mrow[tid] = m;
        lrow[tid] = logf(s);
    }
    __syncthreads();
    if (tid < BB * 11 && tid < out_size) {
        int r = tid / 11;
        out[tid] = L[tid] - mrow[r] - lrow[r];
    }
}

// ---------------- launch ----------------
extern "C" void kernel_launch(void* const* d_in, const int* in_sizes, int n_in,
                              void* d_out, int out_size) {
    const float* x    = (const float*)d_in[0];
    const float* ea   = (const float*)d_in[1];
    const float* we   = (const float*)d_in[2];
    const float* be   = (const float*)d_in[3];
    const float* w1   = (const float*)d_in[4];
    const float* g1   = (const float*)d_in[6];
    const float* be1  = (const float*)d_in[7];
    const float* w2   = (const float*)d_in[8];
    const float* g2   = (const float*)d_in[10];
    const float* be2  = (const float*)d_in[11];
    const float* w3   = (const float*)d_in[12];
    const float* g3   = (const float*)d_in[14];
    const float* be3  = (const float*)d_in[15];
    const float* wf1  = (const float*)d_in[16];
    const float* gf1  = (const float*)d_in[18];
    const float* bef1 = (const float*)d_in[19];
    const float* wf2  = (const float*)d_in[20];
    const float* gf2  = (const float*)d_in[22];
    const float* bef2 = (const float*)d_in[23];
    const float* wf3  = (const float*)d_in[24];
    const float* bf3  = (const float*)d_in[25];
    const int*   ei   = (const int*)d_in[26];
    const int*   batch= (const int*)d_in[27];
    float* out = (float*)d_out;

    void *pz, *pa, *pb, *po1, *po2;
    cudaGetSymbolAddress(&pz, g_zb);
    cudaGetSymbolAddress(&pa, g_bufA);
    cudaGetSymbolAddress(&pb, g_bufB);
    cudaGetSymbolAddress(&po1, g_o1);
    cudaGetSymbolAddress(&po2, g_o2);
    unsigned* zb = (unsigned*)pz;
    float* degsum = (float*)zb;
    int* cnt = (int*)(zb + NN);
    float* stats = (float*)(zb + 2 * NN);          // S1@0, S2@128, S3@256 (sum@+0, sq@+64)
    unsigned* embu = zb + 2 * NN + 384;
    float* bufA = (float*)pa;
    float* bufB = (float*)pb;
    __half* bufAh = (__half*)pa;                   // layer2 output stored as half
    float* o1 = (float*)po1;
    float* o2 = (float*)po2;

    cudaMemsetAsync(pz, 0, sizeof(unsigned) * (2 * NN + 384 + BB * 64));
    k_edgexw1<<<EE / 256 + NN / 8, 256>>>(ea, we, be, ei, x, w1, degsum, cnt);
    // layer 1: spmm over x@w1 (32 chains, premultiplies weights), BN1 stats
    k_spmm1<<<NN / 8, 256>>>(bufA, bufB, cnt, degsum, stats);
    // layer 2: spmm(BN1+relu, 32 chains) + dense 32->64 -> HALF output, BN2 stats
    k_sd32<<<NN / 8, 256>>>(bufB, w2, bufAh, cnt, degsum, stats, g1, be1, stats + 128);
    // layer 3: spmm(BN2+relu over half input, 16 chains) + dense 64->64, BN3 stats
    k_sd64<<<NN / 8, 256>>>(bufAh, w3, bufB, cnt, degsum, stats + 128, g2, be2, stats + 256);
    // BN3 + relu + two-stage global max pool
    k_pool<<<NN / 32, 256>>>(bufB, batch, stats + 256, g3, be3, embu);
    // MLP head (emb conversion + emb output fused into mlp1)
    k_mlp<64, 512, true><<<32, 256>>>(embu, wf1, gf1, bef1, o1, out, out_size);
    k_mlp<512, 256, false><<<16, 256>>>(o1, wf2, gf2, bef2, o2, out, out_size);
    k_head<<<1, 192>>>(o2, wf3, bf3, out, out_size);
}